// round 17
// baseline (speedup 1.0000x reference)
#include <cuda_runtime.h>
#include <math_constants.h>
#include <stdint.h>

#define BB 2
#define SS 2048
#define DD 1024
#define HH 16
#define DHH 64
#define SCALE 0.125f  // DH^-0.5

// ---------------- scratch (no allocations allowed) ----------------
__device__ float g_xt[BB * SS * DD];                     // x, tf32-rounded
__device__ float g_w[4 * DD * DD];                       // wq,wk,wv,wo tf32-rounded
__device__ float g_bqk[2 * DD];                          // packed q,k biases
__device__ float g_qk[2 * BB * SS * DD];                 // q then k (rounded)
__device__ float g_vt[BB * DD * SS];                     // v transposed [b*D+d][s] (rounded)
__device__ float g_ctx[BB * SS * DD];                    // context (rounded)
__device__ float g_ps[(long long)BB * HH * SS * 16];     // per-row partial expsums (4MB)
__device__ float g_inv[BB * HH * SS];                    // 1/rowsum
__device__ float g_attn[(long long)BB * HH * SS * SS];   // fallback if attn not exported

// ---------------- tf32 helpers ----------------
__device__ __forceinline__ float f2tf(float x) {
    uint32_t u;
    asm("cvt.rna.tf32.f32 %0, %1;" : "=r"(u) : "f"(x));
    return __uint_as_float(u);
}

__device__ __forceinline__ void mma8(float* c, const uint32_t* a, const uint32_t* b) {
    asm volatile(
        "mma.sync.aligned.m16n8k8.row.col.f32.tf32.tf32.f32 "
        "{%0,%1,%2,%3}, {%4,%5,%6,%7}, {%8,%9}, {%0,%1,%2,%3};\n"
        : "+f"(c[0]), "+f"(c[1]), "+f"(c[2]), "+f"(c[3])
        : "r"(a[0]), "r"(a[1]), "r"(a[2]), "r"(a[3]),
          "r"(b[0]), "r"(b[1]));
}

__device__ __forceinline__ void cpa16(uint32_t s, const void* g) {
    asm volatile("cp.async.cg.shared.global [%0], [%1], 16;" :: "r"(s), "l"(g) : "memory");
}
__device__ __forceinline__ void cp_commit() {
    asm volatile("cp.async.commit_group;" ::: "memory");
}
template <int N>
__device__ __forceinline__ void cp_wait() {
    asm volatile("cp.async.wait_group %0;" :: "n"(N) : "memory");
}

// ---------------- prep kernels ----------------
__global__ void conv_tf32(const float4* __restrict__ src, float4* __restrict__ dst, int n4) {
    int i = blockIdx.x * 256 + threadIdx.x;
    if (i < n4) {
        float4 v = src[i];
        v.x = f2tf(v.x); v.y = f2tf(v.y); v.z = f2tf(v.z); v.w = f2tf(v.w);
        dst[i] = v;
    }
}
__global__ void conv_tf32_w(const float4* __restrict__ w0, const float4* __restrict__ w1,
                            const float4* __restrict__ w2, const float4* __restrict__ w3,
                            float4* __restrict__ dst, int n4) {
    int i = blockIdx.x * 256 + threadIdx.x;
    if (i >= n4) return;
    const float4* src = (blockIdx.z == 0) ? w0 : (blockIdx.z == 1) ? w1
                       : (blockIdx.z == 2) ? w2 : w3;
    float4 v = src[i];
    v.x = f2tf(v.x); v.y = f2tf(v.y); v.z = f2tf(v.z); v.w = f2tf(v.w);
    dst[(long long)blockIdx.z * n4 + i] = v;
}
__global__ void pack_bias2(const float* __restrict__ a, const float* __restrict__ b,
                           float* __restrict__ dst) {
    int i = blockIdx.x * 256 + threadIdx.x;
    if (i < DD) { dst[i] = a[i]; dst[DD + i] = b[i]; }
}
// inv[r] = 1 / sum of 16 partials (deterministic order)
__global__ void row_inv(const float* __restrict__ ps, float* __restrict__ inv, int nrows) {
    int r = blockIdx.x * 256 + threadIdx.x;
    if (r < nrows) {
        const float4* p = (const float4*)(ps + (long long)r * 16);
        float4 a = p[0], b = p[1], c = p[2], d = p[3];
        float s = ((a.x + a.y) + (a.z + a.w)) + ((b.x + b.y) + (b.z + b.w))
                + ((c.x + c.y) + (c.z + c.w)) + ((d.x + d.y) + (d.z + d.w));
        inv[r] = 1.0f / s;
    }
}

// =================================================================
// TF32 GEMM, cp.async double-buffered.
//   A: [m][k] k-contig, B: [n][k] k-contig. C = alpha*A.B^T (+bias)
//   smem rows chunk-XOR swizzled.
//   CONVA  : tf32-round A fragments at load
//   ROUND_C: tf32-round outputs at store
//   TRANS_C: scatter-store C transposed into g_vt layout
//   SOFTEXP: epilogue = mask + exp(alpha*s); writes p; emits row partial
//            sums to psp[(z*SS+row)*16 + blockIdx.x]
//   PSCALE : A is unnormalized p; stream attn_out = p*inv per k-tile;
//            epilogue scales by inv[row]
// =================================================================
template <int BM, int BN, int BK, int WM, int WN,
          bool CONVA, bool ROUND_C, bool TRANS_C, bool SOFTEXP, bool PSCALE>
__global__ __launch_bounds__(256, 2) void gemm_cp(
    const float* __restrict__ A, const float* __restrict__ Bm,
    const float* __restrict__ bias, float* __restrict__ C,
    int K, int lda, int ldbn, int ldc,
    long long aS1, long long aS2,
    long long bS1, long long bS2,
    long long cS1, long long cS2,
    long long biasS1, int Z2,
    float alpha,
    const int* __restrict__ msk, const float* __restrict__ invp,
    float* __restrict__ psp, float* __restrict__ attnw)
{
    constexpr int WARPS_M = BM / WM;
    constexpr int MT = WM / 16;
    constexpr int NT = WN / 8;
    constexpr int AF = BM / 32;
    constexpr int BF = BN / 32;

    int z = blockIdx.z;
    int z1 = z / Z2, z2 = z % Z2;
    A  += z1 * aS1 + z2 * aS2;
    Bm += z1 * bS1 + z2 * bS2;
    C  += z1 * cS1 + z2 * cS2;
    if (PSCALE) attnw += z1 * aS1 + z2 * aS2;   // same layout as A
    const float* biasp = bias ? bias + z1 * biasS1 : nullptr;

    __shared__ float As[2][BM * BK];
    __shared__ float Bs[2][BN * BK];
    __shared__ float sps[4][BM];    // SOFTEXP partials
    __shared__ float sinv[BM];      // PSCALE row inverses

    int tid  = threadIdx.x;
    int lane = tid & 31, warp = tid >> 5;
    int gid = lane >> 2, tig = lane & 3;
    int warp_m = (warp % WARPS_M) * WM;
    int warp_n = (warp / WARPS_M) * WN;
    int m0 = blockIdx.y * BM, n0 = blockIdx.x * BN;

    if (PSCALE && tid < BM)
        sinv[tid] = invp[(long long)z * SS + m0 + tid];

    int rbase = tid >> 3;
    int cch   = tid & 7;
    int scol  = ((cch ^ (rbase & 7)) << 2);
    uint32_t sA0 = (uint32_t)__cvta_generic_to_shared(&As[0][0]);
    uint32_t sB0 = (uint32_t)__cvta_generic_to_shared(&Bs[0][0]);
    uint32_t sAoff = (uint32_t)((rbase * BK + scol) * 4);

    int kt_total = K / BK;

    auto load_stage = [&](int st, int k0) {
        uint32_t sa = sA0 + st * (BM * BK * 4) + sAoff;
        const float* ga = A + (long long)(m0 + rbase) * lda + k0 + cch * 4;
        #pragma unroll
        for (int i = 0; i < AF; i++)
            cpa16(sa + i * 32 * BK * 4, ga + (long long)i * 32 * lda);
        uint32_t sb = sB0 + st * (BN * BK * 4) + sAoff;
        const float* gb = Bm + (long long)(n0 + rbase) * ldbn + k0 + cch * 4;
        #pragma unroll
        for (int i = 0; i < BF; i++)
            cpa16(sb + i * 32 * BK * 4, gb + (long long)i * 32 * ldbn);
    };

    float acc[MT][NT][4] = {};
    int mb[MT], nb[NT];
    #pragma unroll
    for (int i = 0; i < MT; i++) mb[i] = warp_m + i * 16 + gid;
    #pragma unroll
    for (int j = 0; j < NT; j++) nb[j] = warp_n + j * 8 + gid;

    load_stage(0, 0);
    cp_commit();

    for (int kt = 0; kt < kt_total; kt++) {
        int cur = kt & 1;
        if (kt + 1 < kt_total) {
            load_stage(cur ^ 1, (kt + 1) * BK);
            cp_commit();
            cp_wait<1>();
        } else {
            cp_wait<0>();
        }
        __syncthreads();

        const float* Ac = As[cur];
        const float* Bc = Bs[cur];

        if (PSCALE) {
            // stream normalized attn out of the p tile just loaded
            int k0 = kt * BK;
            #pragma unroll
            for (int i = 0; i < AF; i++) {
                int row = rbase + i * 32;
                float4 p4 = *(const float4*)&Ac[row * BK + scol];
                float iv = sinv[row];
                p4.x *= iv; p4.y *= iv; p4.z *= iv; p4.w *= iv;
                *(float4*)&attnw[(long long)(m0 + row) * lda + k0 + cch * 4] = p4;
            }
        }

        #pragma unroll
        for (int ks = 0; ks < BK; ks += 8) {
            int c0 = ks >> 2;
            int s0 = ((c0 ^ gid) << 2) + tig;
            int s1 = (((c0 + 1) ^ gid) << 2) + tig;
            uint32_t af[MT][4], bf[NT][2];
            #pragma unroll
            for (int i = 0; i < MT; i++) {
                float a0 = Ac[mb[i] * BK + s0];
                float a1 = Ac[(mb[i] + 8) * BK + s0];
                float a2 = Ac[mb[i] * BK + s1];
                float a3 = Ac[(mb[i] + 8) * BK + s1];
                if (CONVA) { a0 = f2tf(a0); a1 = f2tf(a1); a2 = f2tf(a2); a3 = f2tf(a3); }
                af[i][0] = __float_as_uint(a0);
                af[i][1] = __float_as_uint(a1);
                af[i][2] = __float_as_uint(a2);
                af[i][3] = __float_as_uint(a3);
            }
            #pragma unroll
            for (int j = 0; j < NT; j++) {
                bf[j][0] = __float_as_uint(Bc[nb[j] * BK + s0]);
                bf[j][1] = __float_as_uint(Bc[nb[j] * BK + s1]);
            }
            #pragma unroll
            for (int i = 0; i < MT; i++)
                #pragma unroll
                for (int j = 0; j < NT; j++)
                    mma8(acc[i][j], af[i], bf[j]);
        }
        __syncthreads();
    }

    if (SOFTEXP) {
        // mask + exp epilogue; p out; per-row partial sums
        float rs0[MT], rs1[MT];
        #pragma unroll
        for (int i = 0; i < MT; i++) { rs0[i] = 0.f; rs1[i] = 0.f; }
        #pragma unroll
        for (int i = 0; i < MT; i++) {
            int rl = warp_m + i * 16 + gid;
            int q0r = m0 + rl;
            const int* mr0 = msk + ((long long)z1 * SS + q0r) * SS;
            const int* mr1 = msk + ((long long)z1 * SS + q0r + 8) * SS;
            #pragma unroll
            for (int j = 0; j < NT; j++) {
                int c0 = n0 + warp_n + j * 8 + tig * 2;
                int2 mv0 = *(const int2*)&mr0[c0];
                int2 mv1 = *(const int2*)&mr1[c0];
                float s00 = acc[i][j][0] * alpha, s01 = acc[i][j][1] * alpha;
                float s10 = acc[i][j][2] * alpha, s11 = acc[i][j][3] * alpha;
                float p00 = __expf(mv0.x ? s00 : -1e9f);
                float p01 = __expf(mv0.y ? s01 : -1e9f);
                float p10 = __expf(mv1.x ? s10 : -1e9f);
                float p11 = __expf(mv1.y ? s11 : -1e9f);
                *(float2*)&C[(long long)q0r * ldc + c0]       = make_float2(p00, p01);
                *(float2*)&C[(long long)(q0r + 8) * ldc + c0] = make_float2(p10, p11);
                rs0[i] += p00 + p01;
                rs1[i] += p10 + p11;
            }
        }
        #pragma unroll
        for (int i = 0; i < MT; i++) {
            rs0[i] += __shfl_xor_sync(0xFFFFFFFF, rs0[i], 1);
            rs0[i] += __shfl_xor_sync(0xFFFFFFFF, rs0[i], 2);
            rs1[i] += __shfl_xor_sync(0xFFFFFFFF, rs1[i], 1);
            rs1[i] += __shfl_xor_sync(0xFFFFFFFF, rs1[i], 2);
            if (tig == 0) {
                sps[warp >> 1][warp_m + i * 16 + gid]     = rs0[i];
                sps[warp >> 1][warp_m + i * 16 + gid + 8] = rs1[i];
            }
        }
        __syncthreads();
        if (tid < BM) {
            float s = sps[0][tid] + sps[1][tid] + sps[2][tid] + sps[3][tid];
            psp[((long long)z * SS + m0 + tid) * 16 + blockIdx.x] = s;
        }
        return;
    }

    #pragma unroll
    for (int i = 0; i < MT; i++) {
        int rl = warp_m + i * 16 + gid;
        int r0 = m0 + rl;
        float sc0 = 1.f, sc1 = 1.f;
        if (PSCALE) { sc0 = sinv[rl]; sc1 = sinv[rl + 8]; }
        #pragma unroll
        for (int j = 0; j < NT; j++) {
            int c0 = n0 + warp_n + j * 8 + tig * 2;
            float2 bv = make_float2(0.f, 0.f);
            if (biasp) bv = *(const float2*)&biasp[c0];
            float v00 = acc[i][j][0] * alpha * sc0 + bv.x;
            float v01 = acc[i][j][1] * alpha * sc0 + bv.y;
            float v10 = acc[i][j][2] * alpha * sc1 + bv.x;
            float v11 = acc[i][j][3] * alpha * sc1 + bv.y;
            if (ROUND_C) {
                v00 = f2tf(v00); v01 = f2tf(v01); v10 = f2tf(v10); v11 = f2tf(v11);
            }
            if (TRANS_C) {
                int b0 = r0 >> 11, s0r = r0 & (SS - 1);
                int b1 = (r0 + 8) >> 11, s1r = (r0 + 8) & (SS - 1);
                C[((long long)(b0 * DD + c0)) * SS + s0r]     = v00;
                C[((long long)(b0 * DD + c0 + 1)) * SS + s0r] = v01;
                C[((long long)(b1 * DD + c0)) * SS + s1r]     = v10;
                C[((long long)(b1 * DD + c0 + 1)) * SS + s1r] = v11;
            } else {
                *(float2*)&C[(long long)r0 * ldc + c0]       = make_float2(v00, v01);
                *(float2*)&C[(long long)(r0 + 8) * ldc + c0] = make_float2(v10, v11);
            }
        }
    }
}

// ---------------- launch ----------------
extern "C" void kernel_launch(void* const* d_in, const int* in_sizes, int n_in,
                              void* d_out, int out_size)
{
    const float* x    = (const float*)d_in[0];
    const int*   mask = (const int*)  d_in[1];
    const float* wq_w = (const float*)d_in[2];
    const float* wq_b = (const float*)d_in[3];
    const float* wk_w = (const float*)d_in[4];
    const float* wk_b = (const float*)d_in[5];
    const float* wv_w = (const float*)d_in[6];
    const float* wv_b = (const float*)d_in[7];
    const float* wo_w = (const float*)d_in[8];
    const float* wo_b = (const float*)d_in[9];

    float* out = (float*)d_out;

    const long long OUT_ELEMS  = (long long)BB * SS * DD;
    const long long ATTN_ELEMS = (long long)BB * HH * SS * SS;

    float *xt, *w, *bqk, *qk, *vt, *ctx, *ps, *inv, *attn;
    cudaGetSymbolAddress((void**)&xt,  g_xt);
    cudaGetSymbolAddress((void**)&w,   g_w);
    cudaGetSymbolAddress((void**)&bqk, g_bqk);
    cudaGetSymbolAddress((void**)&qk,  g_qk);
    cudaGetSymbolAddress((void**)&vt,  g_vt);
    cudaGetSymbolAddress((void**)&ctx, g_ctx);
    cudaGetSymbolAddress((void**)&ps,  g_ps);
    cudaGetSymbolAddress((void**)&inv, g_inv);
    if ((long long)out_size >= OUT_ELEMS + ATTN_ELEMS) {
        attn = out + OUT_ELEMS;
    } else {
        cudaGetSymbolAddress((void**)&attn, g_attn);
    }

    const int M = BB * SS;           // 4096
    const int WELE = DD * DD;

    // 0) prep: tf32-round x + weights, pack q/k biases
    conv_tf32<<<(M * DD / 4 + 255) / 256, 256>>>((const float4*)x, (float4*)xt, M * DD / 4);
    {
        dim3 grid((WELE / 4 + 255) / 256, 1, 4);
        conv_tf32_w<<<grid, 256>>>((const float4*)wq_w, (const float4*)wk_w,
                                   (const float4*)wv_w, (const float4*)wo_w,
                                   (float4*)w, WELE / 4);
    }
    pack_bias2<<<(DD + 255) / 256, 256>>>(wq_b, wk_b, bqk);

    // 1) Q and K projections (z=0:Q, z=1:K), rounded outputs
    {
        dim3 grid(DD / 128, M / 128, 2);
        gemm_cp<128, 128, 32, 64, 32, false, true, false, false, false><<<grid, 256>>>(
            xt, w, bqk, qk, DD,
            DD, DD, DD,
            0, 0,
            (long long)WELE, 0,
            (long long)M * DD, 0,
            DD, 1, 1.0f,
            nullptr, nullptr, nullptr, nullptr);
    }
    // 1b) V projection, transposed + rounded into g_vt
    {
        dim3 grid(DD / 128, M / 128, 1);
        gemm_cp<128, 128, 32, 64, 32, false, true, true, false, false><<<grid, 256>>>(
            xt, w + 2 * WELE, wv_b, vt, DD,
            DD, DD, 0,
            0, 0, 0, 0, 0, 0, 0, 1, 1.0f,
            nullptr, nullptr, nullptr, nullptr);
    }

    // 2) scores + mask + exp (unnormalized p into attn buffer) + row partials
    {
        dim3 grid(SS / 128, SS / 128, BB * HH);
        gemm_cp<128, 128, 32, 64, 32, false, false, false, true, false><<<grid, 256>>>(
            qk, qk + (long long)M * DD, nullptr, attn, DHH,
            DD, DD, SS,
            (long long)SS * DD, DHH,
            (long long)SS * DD, DHH,
            (long long)HH * SS * SS, (long long)SS * SS,
            0, HH, SCALE,
            mask, nullptr, ps, nullptr);
    }

    // 3) inv = 1/rowsum (deterministic 16-way reduce)
    row_inv<<<(BB * HH * SS + 255) / 256, 256>>>(ps, inv, BB * HH * SS);

    // 4) ctx = (p @ V) * inv ; stream attn = p*inv out of the same tiles
    {
        dim3 grid(DHH / 64, SS / 128, BB * HH);
        gemm_cp<128, 64, 32, 32, 32, true, true, false, false, true><<<grid, 256>>>(
            attn, vt, nullptr, ctx, SS,
            SS, SS, DD,
            (long long)HH * SS * SS, (long long)SS * SS,
            (long long)DD * SS, (long long)DHH * SS,
            (long long)SS * DD, DHH,
            0, HH, 1.0f,
            nullptr, inv, nullptr, attn);
    }

    // 5) out = ctx @ wo^T + wo_b
    {
        dim3 grid(DD / 128, M / 128, 1);
        gemm_cp<128, 128, 32, 64, 32, false, false, false, false, false><<<grid, 256>>>(
            ctx, w + 3 * WELE, wo_b, out, DD,
            DD, DD, DD,
            0, 0, 0, 0, 0, 0, 0, 1, 1.0f,
            nullptr, nullptr, nullptr, nullptr);
    }
}